// round 12
// baseline (speedup 1.0000x reference)
#include <cuda_runtime.h>
#include <cuda_bf16.h>
#include <math.h>
#include <stdint.h>

#define BATCH 16
#define C512  512
#define L0    80000
#define L1    16000
#define L2    4000
#define L3    2000
#define L4    1000
#define L5    500
#define KSTEP 12
#define HID   256
#define G3    768

// ---------------- scratch ----------------
__device__ float g_buf2[BATCH*C512*L2];
__device__ float g_buf3[BATCH*C512*L3];
__device__ float g_buf4[BATCH*C512*L4];
__device__ float g_buf5[BATCH*C512*L5];
__device__ float g_gi  [BATCH*L5*G3];     // [b][t][g]
__device__ float g_scales[5*C512];
__device__ float g_shifts[5*C512];
__device__ float g_ct  [BATCH*HID];
__device__ float g_enc [KSTEP*BATCH*C512];
__device__ float g_pred[KSTEP*BATCH*C512];
__device__ float g_total[KSTEP*BATCH*BATCH];

// BN partial sums
__device__ float g_psum[512*C512];        // [y][ch]
__device__ float g_psq [512*C512];
__device__ float g_bn0ps[BATCH*C512];     // [b][ch]
__device__ float g_bn0pq[BATCH*C512];

// bf16 hi/lo weights (w2 @0, w345 @2M contiguous, wih @5M)
__device__ __nv_bfloat16 g_wh[6*1024*1024];
__device__ __nv_bfloat16 g_wl[6*1024*1024];
#define WOFF2   0
#define WOFF3   2097152
#define WOFF4   3145728
#define WOFF5   4194304
#define WOFFIH  5242880

// padded bf16 hi/lo activations
#define L1P (L1+4)
#define L2P (L2+2)
#define L3P (L3+2)
#define L4P (L4+2)
__device__ __nv_bfloat16 g_a1h[BATCH*C512*L1P];
__device__ __nv_bfloat16 g_a1l[BATCH*C512*L1P];
__device__ __nv_bfloat16 g_a2h[BATCH*C512*L2P];
__device__ __nv_bfloat16 g_a2l[BATCH*C512*L2P];
__device__ __nv_bfloat16 g_a3h[BATCH*C512*L3P];
__device__ __nv_bfloat16 g_a3l[BATCH*C512*L3P];
__device__ __nv_bfloat16 g_a4h[BATCH*C512*L4P];
__device__ __nv_bfloat16 g_a4l[BATCH*C512*L4P];
__device__ __nv_bfloat16 g_a5h[BATCH*C512*L5];  // masked z (for gi)
__device__ __nv_bfloat16 g_a5l[BATCH*C512*L5];

static __device__ __forceinline__ uint32_t smem_u32(const void* p) {
    return (uint32_t)__cvta_generic_to_shared(p);
}

// ================= prep: conv1 stats-only + wcvt =================
#define WCVT_N 5636096
__global__ void prep_kernel(const float* __restrict__ x, const float* __restrict__ w1,
                            const float* __restrict__ w2, const float* __restrict__ w345,
                            const float* __restrict__ wih) {
    int bx = blockIdx.x;
    int tid = threadIdx.x;
    if (bx < 512) {
        __shared__ float ws[160];
        __shared__ float red[256];
        int b  = bx >> 5;
        int o0 = (bx & 31) * 16;
        if (tid < 160) ws[tid] = w1[o0*10 + tid];
        __syncthreads();
        float ps[16], pq[16];
#pragma unroll
        for (int o = 0; o < 16; o++) { ps[o] = 0.f; pq[o] = 0.f; }
        const float* xb = x + (size_t)b*L0;
        for (int t = tid; t < L1; t += 256) {
            float xr[10];
            int p0 = 5*t - 3;
#pragma unroll
            for (int k = 0; k < 10; k++) {
                int p = p0 + k;
                xr[k] = (p >= 0 && p < L0) ? __ldg(xb + p) : 0.f;
            }
#pragma unroll
            for (int o = 0; o < 16; o++) {
                const float* wr = ws + o*10;
                float s = 0.f;
#pragma unroll
                for (int k = 0; k < 10; k++) s += xr[k]*wr[k];
                ps[o] += s; pq[o] += s*s;
            }
        }
        for (int o = 0; o < 16; o++) {
            red[tid] = ps[o]; __syncthreads();
            for (int off = 128; off > 0; off >>= 1) {
                if (tid < off) red[tid] += red[tid + off];
                __syncthreads();
            }
            if (tid == 0) g_bn0ps[b*C512 + o0 + o] = red[0];
            __syncthreads();
            red[tid] = pq[o]; __syncthreads();
            for (int off = 128; off > 0; off >>= 1) {
                if (tid < off) red[tid] += red[tid + off];
                __syncthreads();
            }
            if (tid == 0) g_bn0pq[b*C512 + o0 + o] = red[0];
            __syncthreads();
        }
    } else {
        int i = (bx - 512)*256 + tid;
        if (i < WCVT_N) {
            float v = (i < 2097152) ? w2[i]
                    : (i < 5242880) ? w345[i - 2097152]
                                    : wih[i - 5242880];
            __nv_bfloat16 h = __float2bfloat16(v);
            g_wh[i] = h;
            g_wl[i] = __float2bfloat16(v - __bfloat162float(h));
        }
    }
}

// ================= bn0 reduce (tiny) =================
__global__ void bn0reduce_kernel(const float* __restrict__ gamma, const float* __restrict__ beta) {
    int c = blockIdx.x*256 + threadIdx.x;
    if (c >= C512) return;
    double s = 0.0, q = 0.0;
    for (int b = 0; b < BATCH; b++) { s += (double)g_bn0ps[b*C512 + c]; q += (double)g_bn0pq[b*C512 + c]; }
    double Bn = (double)BATCH * L1;
    double mean = s / Bn;
    double var  = q / Bn - mean*mean;
    double scd  = (double)gamma[c] / sqrt(var + 1e-5);
    g_scales[c] = (float)scd;
    g_shifts[c] = beta[c] - (float)(mean * scd);
}

// ================= conv1cvt: recompute conv1, bn+relu, write padded bf16 hi/lo =======
__global__ void conv1cvt_kernel(const float* __restrict__ x, const float* __restrict__ w1) {
    __shared__ float ws[160];
    int b  = blockIdx.x >> 5;
    int o0 = (blockIdx.x & 31) * 16;
    int tid = threadIdx.x;
    if (tid < 160) ws[tid] = w1[o0*10 + tid];
    __syncthreads();
    float sc[16], sh[16];
#pragma unroll
    for (int o = 0; o < 16; o++) { sc[o] = g_scales[o0+o]; sh[o] = g_shifts[o0+o]; }
    // zero the 4 pad elems of each of the 16 rows
    __nv_bfloat16 z16 = __float2bfloat16(0.f);
    if (tid < 64) {
        int o = tid >> 2, e = tid & 3;
        int idx = (e < 2) ? e : (L1 + e);     // 0,1,L1+2,L1+3
        size_t base = ((size_t)(b*C512 + o0 + o))*L1P;
        g_a1h[base + idx] = z16;
        g_a1l[base + idx] = z16;
    }
    const float* xb = x + (size_t)b*L0;
    for (int t = tid; t < L1; t += 256) {
        float xr[10];
        int p0 = 5*t - 3;
#pragma unroll
        for (int k = 0; k < 10; k++) {
            int p = p0 + k;
            xr[k] = (p >= 0 && p < L0) ? __ldg(xb + p) : 0.f;
        }
#pragma unroll
        for (int o = 0; o < 16; o++) {
            const float* wr = ws + o*10;
            float s = 0.f;
#pragma unroll
            for (int k = 0; k < 10; k++) s += xr[k]*wr[k];
            float v = fmaxf(s*sc[o] + sh[o], 0.f);
            __nv_bfloat16 hb = __float2bfloat16(v);
            size_t base = ((size_t)(b*C512 + o0 + o))*L1P + t + 2;
            g_a1h[base] = hb;
            g_a1l[base] = __float2bfloat16(v - __bfloat162float(hb));
        }
    }
}

// ================= bncvt: reduce partials -> scales, then convert channel ==========
template<bool MASK>
__global__ void bncvt_kernel(const float* __restrict__ buf, __nv_bfloat16* __restrict__ Oh,
                             __nv_bfloat16* __restrict__ Ol,
                             const float* __restrict__ gamma, const float* __restrict__ beta,
                             int layer, int L, int Lpad, int shift, int Y,
                             const int* __restrict__ ts) {
    __shared__ double rs[256], rq[256];
    __shared__ float sscale, sshift;
    int c = blockIdx.x;
    int tid = threadIdx.x;
    double s = 0.0, q = 0.0;
    for (int y = tid; y < Y; y += 256) {
        s += (double)g_psum[y*C512 + c];
        q += (double)g_psq [y*C512 + c];
    }
    rs[tid] = s; rq[tid] = q;
    __syncthreads();
    for (int off = 128; off > 0; off >>= 1) {
        if (tid < off) { rs[tid] += rs[tid+off]; rq[tid] += rq[tid+off]; }
        __syncthreads();
    }
    if (tid == 0) {
        double Bn = (double)BATCH * L;
        double mean = rs[0] / Bn;
        double var  = rq[0] / Bn - mean*mean;
        double scd  = (double)gamma[c] / sqrt(var + 1e-5);
        g_scales[layer*C512 + c] = (float)scd;
        g_shifts[layer*C512 + c] = beta[c] - (float)(mean * scd);
        sscale = (float)scd;
        sshift = beta[c] - (float)(mean * scd);
    }
    __syncthreads();
    float sc = sscale, sh = sshift;
    for (int b = 0; b < BATCH; b++) {
        const float* ip = buf + ((size_t)(b*C512 + c))*L;
        __nv_bfloat16* oh = Oh + ((size_t)(b*C512 + c))*Lpad;
        __nv_bfloat16* ol = Ol + ((size_t)(b*C512 + c))*Lpad;
        int tsb = MASK ? __ldg(ts + b) : 0;
        for (int qq = tid; qq < Lpad; qq += 256) {
            int p = qq - shift;
            float v = 0.f;
            if (p >= 0 && p < L) {
                bool ok = !MASK || (p <= tsb);
                if (ok) v = fmaxf(ip[p]*sc + sh, 0.f);
            }
            __nv_bfloat16 hb = __float2bfloat16(v);
            oh[qq] = hb;
            ol[qq] = __float2bfloat16(v - __bfloat162float(hb));
        }
    }
}

// ================= mma.sync / ldmatrix helpers =================
#define MMA16816(d, a, b) \
    asm volatile( \
        "mma.sync.aligned.m16n8k16.row.col.f32.bf16.bf16.f32 " \
        "{%0,%1,%2,%3}, {%4,%5,%6,%7}, {%8,%9}, {%0,%1,%2,%3};" \
        : "+f"((d)[0]), "+f"((d)[1]), "+f"((d)[2]), "+f"((d)[3]) \
        : "r"((a)[0]), "r"((a)[1]), "r"((a)[2]), "r"((a)[3]), \
          "r"((b)[0]), "r"((b)[1]))

#define LDSM4(r0, r1, r2, r3, addr) \
    asm volatile("ldmatrix.sync.aligned.m8n8.x4.shared.b16 {%0,%1,%2,%3}, [%4];" \
        : "=r"(r0), "=r"(r1), "=r"(r2), "=r"(r3) : "r"(addr))

static __device__ __forceinline__ void cpa4(uint32_t dst, const void* src, uint32_t sz) {
    asm volatile("cp.async.ca.shared.global [%0], [%1], 4, %2;"
                 :: "r"(dst), "l"(src), "r"(sz) : "memory");
}
static __device__ __forceinline__ void cpa8(uint32_t dst, const void* src, uint32_t sz) {
    asm volatile("cp.async.ca.shared.global [%0], [%1], 8, %2;"
                 :: "r"(dst), "l"(src), "r"(sz) : "memory");
}
static __device__ __forceinline__ void cpa16(uint32_t dst, const void* src) {
    asm volatile("cp.async.cg.shared.global [%0], [%1], 16;"
                 :: "r"(dst), "l"(src) : "memory");
}

// ================= pipelined bf16 conv-as-GEMM (cp.async + ldmatrix, 2 CTAs/SM) ======
#define STG_ELEMS 20480
#define DYN_SMEM  (2*STG_ELEMS*2)

template<int KW, int S, int P, int SHIFT>
__global__ void __launch_bounds__(256, 2) mmaconv_bf_kernel(
    const __nv_bfloat16* __restrict__ Inh, const __nv_bfloat16* __restrict__ Inl,
    const __nv_bfloat16* __restrict__ Wh,  const __nv_bfloat16* __restrict__ Wl,
    float* __restrict__ Out,
    int Lpad, int O, int Lout, int Kd, int Ntot)
{
    extern __shared__ __align__(16) __nv_bfloat16 dyn[];
    const int tid  = threadIdx.x;
    const int lane = tid & 31, w = tid >> 5;
    const int wm = (w >> 2) * 64, wn = (w & 3) * 32;
    const int m0 = blockIdx.x * 128, n0 = blockIdx.y * 128;
    const int g = lane >> 2, tig = lane & 3;
    const int C = Kd >> 5;

    const int lq = lane >> 3, lr = lane & 7;
    const int a_loff = ((lq & 1)*8 + lr)*40 + (lq >> 1)*8;
    const int b_loff = ((lq >> 1)*8 + lr)*40 + (lq & 1)*8;

    const int ITS = 16 / KW;
    const int bnn = tid & 127;
    const int clbase = tid >> 7;
    int bq;
    uint32_t bsz4, bsz8;
    {
        int n = n0 + bnn;
        bool vn = (n < Ntot);
        int nv = vn ? n : 0;
        int b = nv / Lout, t = nv - b*Lout;
        bsz4 = vn ? 4u : 0u;
        bsz8 = vn ? 8u : 0u;
        bq = (b*C512)*Lpad + S*t - P + SHIFT;
    }
    const int arow = tid >> 1, ahalf = tid & 1;

    auto load_chunk = [&](int c, int s) {
        __nv_bfloat16* stg = dyn + s*STG_ELEMS;
        const int k0 = c << 5;
        {
            const __nv_bfloat16* srcH = Wh + (size_t)(m0 + arow)*Kd + k0 + ahalf*16;
            const __nv_bfloat16* srcL = Wl + (size_t)(m0 + arow)*Kd + k0 + ahalf*16;
            uint32_t dH = smem_u32(stg + 10240 + arow*40 + ahalf*16);
            uint32_t dL = smem_u32(stg + 15360 + arow*40 + ahalf*16);
            cpa16(dH, srcH);      cpa16(dH + 16, srcH + 8);
            cpa16(dL, srcL);      cpa16(dL + 16, srcL + 8);
        }
        {
            const int c0 = k0 / KW;
#pragma unroll
            for (int it = 0; it < ITS; it++) {
                int cl = it*2 + clbase;
                int srcbase = bq + (c0 + cl)*Lpad;
                uint32_t dH = smem_u32(stg +        bnn*40 + cl*KW);
                uint32_t dL = smem_u32(stg + 5120 + bnn*40 + cl*KW);
                if (KW == 8) {
                    cpa8(dH,     Inh + srcbase,     bsz8);
                    cpa8(dH + 8, Inh + srcbase + 4, bsz8);
                    cpa8(dL,     Inl + srcbase,     bsz8);
                    cpa8(dL + 8, Inl + srcbase + 4, bsz8);
                } else {
#pragma unroll
                    for (int j = 0; j < KW/2; j++) {
                        cpa4(dH + j*4, Inh + srcbase + 2*j, bsz4);
                        cpa4(dL + j*4, Inl + srcbase + 2*j, bsz4);
                    }
                }
            }
        }
        asm volatile("cp.async.commit_group;" ::: "memory");
    };

    float acc[4][4][4];
#pragma unroll
    for (int i = 0; i < 4; i++)
#pragma unroll
        for (int j = 0; j < 4; j++)
#pragma unroll
            for (int q = 0; q < 4; q++) acc[i][j][q] = 0.f;

    load_chunk(0, 0);

    for (int c = 0; c < C; c++) {
        const int s = c & 1;
        if (c + 1 < C) {
            load_chunk(c + 1, s ^ 1);
            asm volatile("cp.async.wait_group 1;" ::: "memory");
        } else {
            asm volatile("cp.async.wait_group 0;" ::: "memory");
        }
        __syncthreads();

        const __nv_bfloat16* stg = dyn + s*STG_ELEMS;
        const uint32_t uBh = smem_u32(stg)         + (wn*40 + b_loff)*2;
        const uint32_t uBl = smem_u32(stg + 5120)  + (wn*40 + b_loff)*2;
        const uint32_t uAh = smem_u32(stg + 10240) + (wm*40 + a_loff)*2;
        const uint32_t uAl = smem_u32(stg + 15360) + (wm*40 + a_loff)*2;

#pragma unroll
        for (int ks = 0; ks < 32; ks += 16) {
            uint32_t ah[4][4], al[4][4], bh[4][2], bl[4][2];
#pragma unroll
            for (int mt = 0; mt < 4; mt++) {
                LDSM4(ah[mt][0], ah[mt][1], ah[mt][2], ah[mt][3], uAh + (mt*640 + ks)*2);
                LDSM4(al[mt][0], al[mt][1], al[mt][2], al[mt][3], uAl + (mt*640 + ks)*2);
            }
            LDSM4(bh[0][0], bh[0][1], bh[1][0], bh[1][1], uBh + ks*2);
            LDSM4(bh[2][0], bh[2][1], bh[3][0], bh[3][1], uBh + (640 + ks)*2);
            LDSM4(bl[0][0], bl[0][1], bl[1][0], bl[1][1], uBl + ks*2);
            LDSM4(bl[2][0], bl[2][1], bl[3][0], bl[3][1], uBl + (640 + ks)*2);
#pragma unroll
            for (int mt = 0; mt < 4; mt++)
#pragma unroll
                for (int nt = 0; nt < 4; nt++) MMA16816(acc[mt][nt], ah[mt], bh[nt]);
#pragma unroll
            for (int mt = 0; mt < 4; mt++)
#pragma unroll
                for (int nt = 0; nt < 4; nt++) MMA16816(acc[mt][nt], al[mt], bh[nt]);
#pragma unroll
            for (int mt = 0; mt < 4; mt++)
#pragma unroll
                for (int nt = 0; nt < 4; nt++) MMA16816(acc[mt][nt], ah[mt], bl[nt]);
        }
        __syncthreads();
    }

    // ---- epilogue: global stores ----
#pragma unroll
    for (int mt = 0; mt < 4; mt++) {
        int r = m0 + wm + mt*16 + g;
#pragma unroll
        for (int nt = 0; nt < 4; nt++) {
            int cc = n0 + wn + nt*8 + tig*2;
#pragma unroll
            for (int q = 0; q < 4; q++) {
                int n  = cc + (q & 1);
                int rr = r + (q >> 1)*8;
                if (n < Ntot) {
                    int b = n / Lout, t = n - b*Lout;
                    Out[((size_t)(b*O + rr))*Lout + t] = acc[mt][nt][q];
                }
            }
        }
    }

    // ---- epilogue: BN partial sums (invalid-n accs are exact zeros) ----
    {
        float s1[8], s2[8];
#pragma unroll
        for (int i = 0; i < 8; i++) { s1[i] = 0.f; s2[i] = 0.f; }
#pragma unroll
        for (int mt = 0; mt < 4; mt++)
#pragma unroll
            for (int nt = 0; nt < 4; nt++)
#pragma unroll
                for (int q = 0; q < 4; q++) {
                    int ri = mt*2 + (q >> 1);
                    float v = acc[mt][nt][q];
                    s1[ri] += v;
                    s2[ri] += v*v;
                }
#pragma unroll
        for (int i = 0; i < 8; i++) {
            s1[i] += __shfl_xor_sync(0xffffffffu, s1[i], 1);
            s1[i] += __shfl_xor_sync(0xffffffffu, s1[i], 2);
            s2[i] += __shfl_xor_sync(0xffffffffu, s2[i], 1);
            s2[i] += __shfl_xor_sync(0xffffffffu, s2[i], 2);
        }
        float* sp = (float*)dyn;
        if (tig == 0) {
#pragma unroll
            for (int mt = 0; mt < 4; mt++)
#pragma unroll
                for (int h = 0; h < 2; h++) {
                    int row = wm + mt*16 + g + h*8;
                    sp[row*4 + (w & 3)]       = s1[mt*2 + h];
                    sp[512 + row*4 + (w & 3)] = s2[mt*2 + h];
                }
        }
        __syncthreads();
        if (tid < 128) {
            float a = sp[tid*4] + sp[tid*4+1] + sp[tid*4+2] + sp[tid*4+3];
            float b = sp[512 + tid*4] + sp[512 + tid*4+1] + sp[512 + tid*4+2] + sp[512 + tid*4+3];
            g_psum[blockIdx.y*C512 + m0 + tid] = a;
            g_psq [blockIdx.y*C512 + m0 + tid] = b;
        }
    }
}

// ================= mmaconv for gi (KW=1, reads pre-masked bf16) =================
#define SMSTRIDE 34
__global__ void __launch_bounds__(256, 2) mmaconv_gi_kernel(
    const __nv_bfloat16* __restrict__ Inh, const __nv_bfloat16* __restrict__ Inl,
    const __nv_bfloat16* __restrict__ Wh,  const __nv_bfloat16* __restrict__ Wl,
    float* __restrict__ Out,
    int Cin, int Lin, int O, int Lout, int Kd, int Ntot)
{
    __shared__ __nv_bfloat16 sAh[128][SMSTRIDE];
    __shared__ __nv_bfloat16 sAl[128][SMSTRIDE];
    __shared__ __nv_bfloat16 sBh[128][SMSTRIDE];
    __shared__ __nv_bfloat16 sBl[128][SMSTRIDE];
    const int tid  = threadIdx.x;
    const int lane = tid & 31, w = tid >> 5;
    const int wm = (w >> 2) * 64, wn = (w & 3) * 32;
    const int m0 = blockIdx.x * 128, n0 = blockIdx.y * 128;
    const int g = lane >> 2, tig = lane & 3;
    const int arow = tid >> 1, ak0 = (tid & 1) * 16;
    const int nchunks = Kd >> 5;

    float acc[4][4][4];
#pragma unroll
    for (int i = 0; i < 4; i++)
#pragma unroll
        for (int j = 0; j < 4; j++)
#pragma unroll
            for (int q = 0; q < 4; q++) acc[i][j][q] = 0.f;

    for (int c = 0; c < nchunks; c++) {
        const int k0 = c << 5;
        {
            const size_t go = (size_t)(m0 + arow)*Kd + k0 + ak0;
            uint4 ha = *(const uint4*)(Wh + go);
            uint4 hb = *(const uint4*)(Wh + go + 8);
            uint4 la = *(const uint4*)(Wl + go);
            uint4 lb = *(const uint4*)(Wl + go + 8);
            uint32_t* dh = (uint32_t*)&sAh[arow][ak0];
            uint32_t* dl = (uint32_t*)&sAl[arow][ak0];
            dh[0]=ha.x; dh[1]=ha.y; dh[2]=ha.z; dh[3]=ha.w;
            dh[4]=hb.x; dh[5]=hb.y; dh[6]=hb.z; dh[7]=hb.w;
            dl[0]=la.x; dl[1]=la.y; dl[2]=la.z; dl[3]=la.w;
            dl[4]=lb.x; dl[5]=lb.y; dl[6]=lb.z; dl[7]=lb.w;
        }
        {
#pragma unroll
            for (int it = 0; it < 16; it++) {
                int idx = it*256 + tid;
                int nn = idx & 127;
                int cl = idx >> 7;
                int cch = k0 + cl;
                int n = n0 + nn;
                bool vn = (n < Ntot);
                __nv_bfloat16 hv, lv;
                *(uint16_t*)&hv = 0; *(uint16_t*)&lv = 0;
                if (vn) {
                    int b = n / Lout, t = n - b*Lout;
                    size_t off = ((size_t)(b*Cin + cch))*Lin + t;
                    hv = __ldg(Inh + off);
                    lv = __ldg(Inl + off);
                }
                sBh[nn][cl] = hv;
                sBl[nn][cl] = lv;
            }
        }
        __syncthreads();
#pragma unroll
        for (int ks = 0; ks < 32; ks += 16) {
            const int cb = ks + tig*2;
            uint32_t ah[4][4], al[4][4], bh[4][2];
#pragma unroll
            for (int mt = 0; mt < 4; mt++) {
                int r = wm + mt*16 + g;
                ah[mt][0] = *(const uint32_t*)&sAh[r][cb];
                ah[mt][1] = *(const uint32_t*)&sAh[r+8][cb];
                ah[mt][2] = *(const uint32_t*)&sAh[r][cb+8];
                ah[mt][3] = *(const uint32_t*)&sAh[r+8][cb+8];
                al[mt][0] = *(const uint32_t*)&sAl[r][cb];
                al[mt][1] = *(const uint32_t*)&sAl[r+8][cb];
                al[mt][2] = *(const uint32_t*)&sAl[r][cb+8];
                al[mt][3] = *(const uint32_t*)&sAl[r+8][cb+8];
            }
#pragma unroll
            for (int nt = 0; nt < 4; nt++) {
                int rn = wn + nt*8 + g;
                bh[nt][0] = *(const uint32_t*)&sBh[rn][cb];
                bh[nt][1] = *(const uint32_t*)&sBh[rn][cb+8];
            }
#pragma unroll
            for (int mt = 0; mt < 4; mt++)
#pragma unroll
                for (int nt = 0; nt < 4; nt++) MMA16816(acc[mt][nt], ah[mt], bh[nt]);
#pragma unroll
            for (int mt = 0; mt < 4; mt++)
#pragma unroll
                for (int nt = 0; nt < 4; nt++) MMA16816(acc[mt][nt], al[mt], bh[nt]);
            uint32_t bl[4][2];
#pragma unroll
            for (int nt = 0; nt < 4; nt++) {
                int rn = wn + nt*8 + g;
                bl[nt][0] = *(const uint32_t*)&sBl[rn][cb];
                bl[nt][1] = *(const uint32_t*)&sBl[rn][cb+8];
            }
#pragma unroll
            for (int mt = 0; mt < 4; mt++)
#pragma unroll
                for (int nt = 0; nt < 4; nt++) MMA16816(acc[mt][nt], ah[mt], bl[nt]);
        }
        __syncthreads();
    }
#pragma unroll
    for (int mt = 0; mt < 4; mt++) {
        int r = m0 + wm + mt*16 + g;
#pragma unroll
        for (int nt = 0; nt < 4; nt++) {
            int cc = n0 + wn + nt*8 + tig*2;
#pragma unroll
            for (int q = 0; q < 4; q++) {
                int n  = cc + (q & 1);
                int rr = r + (q >> 1)*8;
                if (n < Ntot) {
                    int b = n / Lout, t = n - b*Lout;
                    Out[((size_t)b*Lout + t)*O + rr] = acc[mt][nt][q];
                }
            }
        }
    }
}

// ================= GRU: 8-CTA cluster per batch, DSMEM h exchange =================
static __device__ __forceinline__ void dsmem_store(uint32_t laddr, uint32_t rank, float v) {
    uint32_t dst;
    asm volatile("mapa.shared::cluster.u32 %0, %1, %2;" : "=r"(dst) : "r"(laddr), "r"(rank));
    asm volatile("st.shared::cluster.f32 [%0], %1;" :: "r"(dst), "f"(v) : "memory");
}
#define CLUSTER_SYNC() do { \
    asm volatile("barrier.cluster.arrive.aligned;" ::: "memory"); \
    asm volatile("barrier.cluster.wait.aligned;" ::: "memory"); } while(0)

__global__ void __cluster_dims__(8,1,1) gru_kernel(
    const float* __restrict__ gi, const float* __restrict__ whh,
    const float* __restrict__ bih, const float* __restrict__ bhh,
    const int* __restrict__ ts, const float* __restrict__ hidden,
    float* __restrict__ out)
{
    extern __shared__ float smg[];
    float* Ws   = smg;
    float* hs   = smg + 96*256;
    float* gh_s = hs + 512;
    uint32_t rank;
    asm("mov.u32 %0, %%cluster_ctarank;" : "=r"(rank));
    int b  = blockIdx.x >> 3;
    int j0 = rank * 32;
    int tid = threadIdx.x;
    int warp = tid >> 5, lane = tid & 31;

    for (int e = tid; e < 96*256; e += 128) {
        int gate = e >> 13;
        int rem  = e & 8191;
        int j    = rem >> 8;
        int k    = rem & 255;
        Ws[((gate*64 + (k>>2))*32 + j)*4 + (k&3)] = whh[((size_t)(gate*256 + j0 + j))*256 + k];
    }
    for (int e = tid; e < HID; e += 128) hs[e] = hidden[b*HID + e];
    int tsb = ts[b];
    float bihr=0.f,bihz=0.f,bihn=0.f,bhhr=0.f,bhhz=0.f,bhhn=0.f;
    if (warp == 0) {
        bihr = bih[j0+lane]; bihz = bih[256+j0+lane]; bihn = bih[512+j0+lane];
        bhhr = bhh[j0+lane]; bhhz = bhh[256+j0+lane]; bhhn = bhh[512+j0+lane];
    }
    __syncthreads();
    CLUSTER_SYNC();

    for (int t = 0; t < L5; t++) {
        const float* hcur = hs + (t & 1)*256;
        if (warp < 3) {
            const float4* wp = (const float4*)Ws + warp*2048 + lane;
            const float4* hp = (const float4*)hcur;
            float acc = 0.f;
#pragma unroll
            for (int k4 = 0; k4 < 64; k4++) {
                float4 w = wp[k4*32];
                float4 h = hp[k4];
                acc += w.x*h.x + w.y*h.y + w.z*h.z + w.w*h.w;
            }
            gh_s[warp*32 + lane] = acc;
        }
        __syncthreads();
        if (warp == 0) {
            int j = j0 + lane;
            const float* gb = gi + ((size_t)b*L5 + t)*G3;
            float gir = gb[j]       + bihr;
            float giz = gb[256 + j] + bihz;
            float gin = gb[512 + j] + bihn;
            float ghr = gh_s[lane]    + bhhr;
            float ghz = gh_s[32+lane] + bhhz;
            float ghn = gh_s[64+lane] + bhhn;
            float r   = 1.f/(1.f + expf(-(gir+ghr)));
            float zg  = 1.f/(1.f + expf(-(giz+ghz)));
            float n   = tanhf(gin + r*ghn);
            float hold = hcur[j];
            float hnew = (1.f - zg)*n + zg*hold;
            uint32_t laddr = smem_u32(hs + ((t+1)&1)*256 + j);
#pragma unroll
            for (int r2 = 0; r2 < 8; r2++) dsmem_store(laddr, (uint32_t)r2, hnew);
            if (t == tsb)   g_ct[b*HID + j] = hnew;
            if (t == L5-1)  out[2 + b*HID + j] = hnew;
        }
        CLUSTER_SYNC();
    }
}

// ================= head =================
__global__ void enc_kernel(const int* __restrict__ ts) {
    int idx = blockIdx.x*blockDim.x + threadIdx.x;
    if (idx >= KSTEP*BATCH*C512) return;
    int d = idx & 511;
    int b = (idx >> 9) & 15;
    int k = idx >> 13;
    int t = ts[b] + k + 1;
    float v = g_buf5[((size_t)b*C512 + d)*L5 + t];
    g_enc[idx] = fmaxf(v*g_scales[4*C512 + d] + g_shifts[4*C512 + d], 0.f);
}

__global__ void pred_kernel(const float* __restrict__ wkw, const float* __restrict__ wkb) {
    int k = blockIdx.x >> 4;
    int b = blockIdx.x & 15;
    __shared__ float cs[HID];
    if (threadIdx.x < HID) cs[threadIdx.x] = g_ct[b*HID + threadIdx.x];
    __syncthreads();
    int d = threadIdx.x;
    const float* wr = wkw + ((size_t)k*C512 + d)*HID;
    float acc = wkb[k*C512 + d];
#pragma unroll 8
    for (int h = 0; h < HID; h++) acc += cs[h]*wr[h];
    g_pred[(k*BATCH + b)*C512 + d] = acc;
}

__global__ void total_kernel() {
    int k = blockIdx.x >> 4;
    int b = blockIdx.x & 15;
    int c = threadIdx.x;
    if (c < BATCH) {
        const float* e = g_enc  + ((size_t)(k*BATCH + b))*C512;
        const float* p = g_pred + ((size_t)(k*BATCH + c))*C512;
        float acc = 0.f;
        for (int d = 0; d < C512; d++) acc += e[d]*p[d];
        g_total[(k*BATCH + b)*BATCH + c] = acc;
    }
}

__global__ void final_kernel(float* __restrict__ out) {
    __shared__ float red[192];
    __shared__ float lse11[16];
    __shared__ float corr[16];
    int tid = threadIdx.x;
    int k = tid >> 4, b = tid & 15;
    float contrib;
    {
        const float* row = g_total + tid*16;
        float mx = row[0];
        for (int c = 1; c < 16; c++) mx = fmaxf(mx, row[c]);
        float s = 0.f;
        for (int c = 0; c < 16; c++) s += expf(row[c]-mx);
        float lse = mx + logf(s);
        contrib = row[b] - lse;
        if (k == KSTEP-1) lse11[b] = lse;
    }
    red[tid] = contrib;
    __syncthreads();
    if (tid < 16) {
        int c = tid;
        const float* t11 = g_total + (KSTEP-1)*BATCH*BATCH;
        float best = -1e30f; int arg = -1;
        for (int bb = 0; bb < 16; bb++) {
            float v = expf(t11[bb*16 + c] - lse11[bb]);
            if (v > best) { best = v; arg = bb; }
        }
        corr[c] = (arg == c) ? 1.f : 0.f;
    }
    __syncthreads();
    if (tid == 0) {
        float s = 0.f;
        for (int i = 0; i < 192; i++) s += red[i];
        out[1] = s / (-1.f * BATCH * KSTEP);
        float a = 0.f;
        for (int i = 0; i < 16; i++) a += corr[i];
        out[0] = a / (float)BATCH;
    }
}

// ================= host =================
extern "C" void kernel_launch(void* const* d_in, const int* in_sizes, int n_in,
                              void* d_out, int out_size) {
    const float* x      = (const float*)d_in[0];
    const float* hidden = (const float*)d_in[1];
    const int*   ts     = (const int*)d_in[3];
    const float* w1     = (const float*)d_in[4];
    const float* w2     = (const float*)d_in[5];
    const float* w345   = (const float*)d_in[6];
    const float* gamma  = (const float*)d_in[7];
    const float* beta   = (const float*)d_in[8];
    const float* wih    = (const float*)d_in[9];
    const float* whh    = (const float*)d_in[10];
    const float* bih    = (const float*)d_in[11];
    const float* bhh    = (const float*)d_in[12];
    const float* wkw    = (const float*)d_in[13];
    const float* wkb    = (const float*)d_in[14];
    float* out = (float*)d_out;

    float *buf2, *buf3, *buf4, *buf5, *gi;
    __nv_bfloat16 *wh, *wl, *a1h, *a1l, *a2h, *a2l, *a3h, *a3l, *a4h, *a4l, *a5h, *a5l;
    cudaGetSymbolAddress((void**)&buf2, g_buf2);
    cudaGetSymbolAddress((void**)&buf3, g_buf3);
    cudaGetSymbolAddress((void**)&buf4, g_buf4);
    cudaGetSymbolAddress((void**)&buf5, g_buf5);
    cudaGetSymbolAddress((void**)&gi,   g_gi);
    cudaGetSymbolAddress((void**)&wh,   g_wh);
    cudaGetSymbolAddress((void**)&wl,   g_wl);
    cudaGetSymbolAddress((void**)&a1h,  g_a1h);
    cudaGetSymbolAddress((void**)&a1l,  g_a1l);
    cudaGetSymbolAddress((void**)&a2h,  g_a2h);
    cudaGetSymbolAddress((void**)&a2l,  g_a2l);
    cudaGetSymbolAddress((void**)&a3h,  g_a3h);
    cudaGetSymbolAddress((void**)&a3l,  g_a3l);
    cudaGetSymbolAddress((void**)&a4h,  g_a4h);
    cudaGetSymbolAddress((void**)&a4l,  g_a4l);
    cudaGetSymbolAddress((void**)&a5h,  g_a5h);
    cudaGetSymbolAddress((void**)&a5l,  g_a5l);

    cudaFuncSetAttribute(mmaconv_bf_kernel<8,4,2,2>, cudaFuncAttributeMaxDynamicSharedMemorySize, DYN_SMEM);
    cudaFuncSetAttribute(mmaconv_bf_kernel<4,2,1,1>, cudaFuncAttributeMaxDynamicSharedMemorySize, DYN_SMEM);

    // [0] prep (conv1 stats-only + wcvt)
    prep_kernel<<<512 + (WCVT_N + 255)/256, 256>>>(x, w1, w2, w345, wih);
    // [1] bn0 reduce  [2] conv1 recompute + bn + convert (no fp32 round-trip)
    bn0reduce_kernel<<<2, 256>>>(gamma, beta);
    conv1cvt_kernel<<<512, 256>>>(x, w1);
    // [3] conv2 (PROFILED)
    mmaconv_bf_kernel<8,4,2,2><<<dim3(4,500), 256, DYN_SMEM>>>(a1h, a1l, wh + WOFF2, wl + WOFF2, buf2, L1P, 512, L2, 4096, BATCH*L2);
    bncvt_kernel<false><<<C512, 256>>>(buf2, a2h, a2l, gamma + 1*C512, beta + 1*C512, 1, L2, L2P, 1, 500, ts);

    mmaconv_bf_kernel<4,2,1,1><<<dim3(4,250), 256, DYN_SMEM>>>(a2h, a2l, wh + WOFF3, wl + WOFF3, buf3, L2P, 512, L3, 2048, BATCH*L3);
    bncvt_kernel<false><<<C512, 256>>>(buf3, a3h, a3l, gamma + 2*C512, beta + 2*C512, 2, L3, L3P, 1, 250, ts);

    mmaconv_bf_kernel<4,2,1,1><<<dim3(4,125), 256, DYN_SMEM>>>(a3h, a3l, wh + WOFF4, wl + WOFF4, buf4, L3P, 512, L4, 2048, BATCH*L4);
    bncvt_kernel<false><<<C512, 256>>>(buf4, a4h, a4l, gamma + 3*C512, beta + 3*C512, 3, L4, L4P, 1, 125, ts);

    mmaconv_bf_kernel<4,2,1,1><<<dim3(4,63), 256, DYN_SMEM>>>(a4h, a4l, wh + WOFF5, wl + WOFF5, buf5, L4P, 512, L5, 2048, BATCH*L5);
    // bn4 stats + masked z for gi (no pad, shift 0)
    bncvt_kernel<true><<<C512, 256>>>(buf5, a5h, a5l, gamma + 4*C512, beta + 4*C512, 4, L5, L5, 0, 63, ts);

    // gi = Wih . masked z  (pre-split bf16 path, [b][t][g] out)
    mmaconv_gi_kernel<<<dim3(6,63), 256>>>(a5h, a5l, wh + WOFFIH, wl + WOFFIH, gi, 512, L5, G3, L5, 512, BATCH*L5);

    // GRU
    int smg = (96*256 + 512 + 96) * (int)sizeof(float);
    cudaFuncSetAttribute(gru_kernel, cudaFuncAttributeMaxDynamicSharedMemorySize, smg);
    gru_kernel<<<128, 128, smg>>>(gi, whh, bih, bhh, ts, hidden, out);

    // head
    enc_kernel<<<(KSTEP*BATCH*C512 + 255)/256, 256>>>(ts);
    pred_kernel<<<KSTEP*BATCH, 512>>>(wkw, wkb);
    total_kernel<<<KSTEP*BATCH, 32>>>();
    final_kernel<<<1, 192>>>(out);
}